// round 9
// baseline (speedup 1.0000x reference)
#include <cuda_runtime.h>
#include <cuda_fp16.h>
#include <cstdint>
#include <math.h>

#define T_STEPS 256
#define B_SZ    1024
#define Y_DIM   32
#define H_DIM   1024
#define R_DIM   512
#define R3      1536
#define YP      64

// ---------------- device-global scratch ----------------
__device__ float  g_h0[B_SZ * R_DIM], g_h1[B_SZ * R_DIM];
__device__ __half g_h0h[B_SZ * R_DIM], g_h1h[B_SZ * R_DIM];
__device__ __half g_d1h[B_SZ * H_DIM], g_d2h[B_SZ * H_DIM];
__device__ float  g_GH0[B_SZ * R3], g_GH1[B_SZ * R3], g_GI1[B_SZ * R3];
__device__ float  g_hp[2 * B_SZ * 64];              // heads K-split partials
__device__ __half g_yh[T_STEPS * B_SZ * YP];
__device__ __half g_GI0[(size_t)T_STEPS * B_SZ * R3];
__device__ double g_nllb[512];
__device__ unsigned int g_bar;

__device__ __half hw_d1[H_DIM * R_DIM];
__device__ __half hw_d2[H_DIM * H_DIM];
__device__ __half hw_hd[128 * H_DIM];
__device__ __half hw_i0[R3 * YP];
__device__ __half hw_g0[R3 * R_DIM];
__device__ __half hw_i1[R3 * R_DIM];
__device__ __half hw_g1[R3 * R_DIM];

struct SmemS { char A[4][16384]; char B[4][16384]; float red[8]; };  // 128KB -> 1 CTA/SM
#define SWZ(o) ((o) ^ (((o) >> 3) & 0x70))

#define M_HRELU 0   // half out, +bias, relu
#define M_FBIAS 1   // float out, +bias
#define M_HBIAS 2   // half out, +bias
#define M_FRAW64 3  // float raw partial, 64-wide

// ---------------- helpers ----------------
__device__ __forceinline__ uint32_t smem_u32(const void* p) {
    uint32_t a;
    asm("{ .reg .u64 t; cvta.to.shared.u64 t, %1; cvt.u32.u64 %0, t; }" : "=r"(a) : "l"(p));
    return a;
}
__device__ __forceinline__ void cp16(uint32_t dst, const void* src) {
    asm volatile("cp.async.cg.shared.global [%0], [%1], 16;" :: "r"(dst), "l"(src));
}
__device__ __forceinline__ void ldsm4(uint32_t& r0, uint32_t& r1, uint32_t& r2,
                                      uint32_t& r3, uint32_t a) {
    asm volatile("ldmatrix.sync.aligned.m8n8.x4.shared.b16 {%0,%1,%2,%3}, [%4];"
                 : "=r"(r0), "=r"(r1), "=r"(r2), "=r"(r3) : "r"(a));
}
__device__ __forceinline__ void mma16816(float* c, uint32_t a0, uint32_t a1,
                                         uint32_t a2, uint32_t a3,
                                         uint32_t b0, uint32_t b1) {
    asm volatile("mma.sync.aligned.m16n8k16.row.col.f32.f16.f16.f32 "
                 "{%0,%1,%2,%3}, {%4,%5,%6,%7}, {%8,%9}, {%0,%1,%2,%3};"
                 : "+f"(c[0]), "+f"(c[1]), "+f"(c[2]), "+f"(c[3])
                 : "r"(a0), "r"(a1), "r"(a2), "r"(a3), "r"(b0), "r"(b1));
}
__device__ __forceinline__ void grid_sync(unsigned int target) {
    __threadfence();
    __syncthreads();
    if (threadIdx.x == 0) {
        atomicAdd(&g_bar, 1u);
        while (*((volatile unsigned int*)&g_bar) < target) { __nanosleep(64); }
        __threadfence();
    }
    __syncthreads();
}

// ---------------- chunk staging: A 128x64h + B 128x64h ----------------
__device__ __forceinline__ void stage_chunk(uint32_t dA, uint32_t dB,
                                            const __half* Ah, int ldA, int bm,
                                            const __half* Wh, int ldW, int k0, int tid) {
#pragma unroll
    for (int i = 0; i < 4; i++) {
        int e = tid + i * 256, r = e >> 3, q = e & 7;
        cp16(dA + SWZ(r * 128 + q * 16), Ah + (size_t)(bm + r) * ldA + k0 + q * 8);
        cp16(dB + SWZ(r * 128 + q * 16), Wh + (size_t)r * ldW + k0 + q * 8);
    }
    asm volatile("cp.async.commit_group;");
}

// ---------------- K-loop: 4-stage pipeline, ONE sync per chunk ----------------
__device__ void run_mma(SmemS* sm, const __half* Ah, int ldA,
                        const __half* Wh, int ldW, int kbase, int klen,
                        int bm, float acc[4][4][4], int tid) {
    uint32_t sA[4] = { smem_u32(sm->A[0]), smem_u32(sm->A[1]),
                       smem_u32(sm->A[2]), smem_u32(sm->A[3]) };
    uint32_t sB[4] = { smem_u32(sm->B[0]), smem_u32(sm->B[1]),
                       smem_u32(sm->B[2]), smem_u32(sm->B[3]) };
    const int lane = tid & 31, w = tid >> 5;
    const int wm = (w >> 2) * 64, wn = (w & 3) * 32;
    const int arow = lane & 15, acol = (lane >> 4) * 16;
    const int brow = (lane & 7) + ((lane & 16) ? 8 : 0);
    const int bcol = (lane & 8) ? 16 : 0;
#pragma unroll
    for (int mt = 0; mt < 4; mt++)
#pragma unroll
        for (int nt = 0; nt < 4; nt++)
#pragma unroll
            for (int i = 0; i < 4; i++) acc[mt][nt][i] = 0.f;

    const int nch = klen >> 6;
    const int pro = nch < 3 ? nch : 3;
    for (int s = 0; s < pro; s++)
        stage_chunk(sA[s], sB[s], Ah, ldA, bm, Wh, ldW, kbase + (s << 6), tid);
    int staged = pro;
    for (int kc = 0; kc < nch; kc++) {
        int pa = staged - kc - 1;
        if (pa >= 2)      asm volatile("cp.async.wait_group 2;");
        else if (pa == 1) asm volatile("cp.async.wait_group 1;");
        else              asm volatile("cp.async.wait_group 0;");
        __syncthreads();
        if (staged < nch) {
            int sb = staged & 3;
            stage_chunk(sA[sb], sB[sb], Ah, ldA, bm, Wh, ldW, kbase + (staged << 6), tid);
            staged++;
        }
        uint32_t aB = sA[kc & 3], bB = sB[kc & 3];
#pragma unroll
        for (int s = 0; s < 4; s++) {
            uint32_t b00, b01, b02, b03, b10, b11, b12, b13;
            ldsm4(b00, b01, b02, b03, bB + SWZ((wn + brow) * 128 + s * 32 + bcol));
            ldsm4(b10, b11, b12, b13, bB + SWZ((wn + 16 + brow) * 128 + s * 32 + bcol));
#pragma unroll
            for (int mt = 0; mt < 4; mt++) {
                uint32_t a0, a1, a2, a3;
                ldsm4(a0, a1, a2, a3, aB + SWZ((wm + mt * 16 + arow) * 128 + s * 32 + acol));
                mma16816(acc[mt][0], a0, a1, a2, a3, b00, b01);
                mma16816(acc[mt][1], a0, a1, a2, a3, b02, b03);
                mma16816(acc[mt][2], a0, a1, a2, a3, b10, b11);
                mma16816(acc[mt][3], a0, a1, a2, a3, b12, b13);
            }
        }
    }
}

// ---------------- epilogue ----------------
__device__ void tile_out(float acc[4][4][4], int mode, const float* bias,
                         float* Cf, __half* Ch, int ldC, int bm, int bn, int tid) {
    const int lane = tid & 31, w = tid >> 5;
    const int wm = (w >> 2) * 64, wn = (w & 3) * 32;
#pragma unroll
    for (int mt = 0; mt < 4; mt++)
#pragma unroll
        for (int nt = 0; nt < 4; nt++) {
            int row = bm + wm + mt * 16 + (lane >> 2);
            int lcol = wn + ((nt >> 1) << 4) + ((nt & 1) << 3) + 2 * (lane & 3);
            int col = bn + lcol;
            float x0 = acc[mt][nt][0], x1 = acc[mt][nt][1];
            float x2 = acc[mt][nt][2], x3 = acc[mt][nt][3];
            if (mode == M_FRAW64) {
                if (lcol < 64) {
                    *(float2*)(Cf + (size_t)row * 64 + lcol)       = make_float2(x0, x1);
                    *(float2*)(Cf + (size_t)(row + 8) * 64 + lcol) = make_float2(x2, x3);
                }
            } else {
                float b0 = bias[col], b1 = bias[col + 1];
                x0 += b0; x1 += b1; x2 += b0; x3 += b1;
                if (mode == M_HRELU) {
                    x0 = fmaxf(x0, 0.f); x1 = fmaxf(x1, 0.f);
                    x2 = fmaxf(x2, 0.f); x3 = fmaxf(x3, 0.f);
                }
                if (mode == M_FBIAS) {
                    *(float2*)(Cf + (size_t)row * ldC + col)       = make_float2(x0, x1);
                    *(float2*)(Cf + (size_t)(row + 8) * ldC + col) = make_float2(x2, x3);
                } else {
                    *(__half2*)(Ch + (size_t)row * ldC + col)       = __floats2half2_rn(x0, x1);
                    *(__half2*)(Ch + (size_t)(row + 8) * ldC + col) = __floats2half2_rn(x2, x3);
                }
            }
        }
}

__device__ __forceinline__ void tile_gemm(SmemS* sm, const __half* Ah, int ldA,
                                          const __half* W, int ldW, int kbase, int klen,
                                          int bm, int bn, int mode, const float* bias,
                                          float* Cf, __half* Ch, int ldC, int tid) {
    float acc[4][4][4];
    run_mma(sm, Ah, ldA, W + (size_t)bn * ldW, ldW, kbase, klen, bm, acc, tid);
    tile_out(acc, mode, bias, Cf, Ch, ldC, bm, bn, tid);
}

// ---------------- elementwise ----------------
__device__ __forceinline__ void gates0_chunk(int t, int c, int tid) {
    int i = c * 256 + tid;
    int b = i >> 9, n = i & 511;
    size_t gio = (size_t)t * (B_SZ * R3) + (size_t)b * R3 + n;
    float gir = __half2float(g_GI0[gio]);
    float giz = __half2float(g_GI0[gio + 512]);
    float gin = __half2float(g_GI0[gio + 1024]);
    size_t o = (size_t)b * R3 + n;
    float ghr = g_GH0[o], ghz = g_GH0[o + 512], ghn = g_GH0[o + 1024];
    float r = 1.0f / (1.0f + expf(-(gir + ghr)));
    float z = 1.0f / (1.0f + expf(-(giz + ghz)));
    float nn = tanhf(gin + r * ghn);
    float out = (1.0f - z) * nn + z * g_h0[i];
    g_h0[i] = out;
    g_h0h[i] = __float2half(out);
}
__device__ __forceinline__ void gates1_chunk(int c, int tid) {
    int i = c * 256 + tid;
    int b = i >> 9, n = i & 511;
    size_t o = (size_t)b * R3 + n;
    float gir = g_GI1[o], giz = g_GI1[o + 512], gin = g_GI1[o + 1024];
    float ghr = g_GH1[o], ghz = g_GH1[o + 512], ghn = g_GH1[o + 1024];
    float r = 1.0f / (1.0f + expf(-(gir + ghr)));
    float z = 1.0f / (1.0f + expf(-(giz + ghz)));
    float nn = tanhf(gin + r * ghn);
    float out = (1.0f - z) * nn + z * g_h1[i];
    g_h1[i] = out;
    g_h1h[i] = __float2half(out);
}
__device__ __forceinline__ void nll_chunk(const float* y, const float* mean_b,
                                          const float* std_b, int tt, int c, int tid,
                                          float& nll_acc) {
    int e = c * 256 + tid;
    int b = e >> 5, yc = e & 31;
    int o = b * 64 + yc;
    float mean = g_hp[o] + g_hp[65536 + o] + mean_b[yc];
    float sv = g_hp[o + 32] + g_hp[65536 + o + 32] + std_b[yc];
    float std = (sv > 15.0f) ? sv : log1pf(expf(sv));
    float diff = y[(size_t)tt * (B_SZ * Y_DIM) + b * 32 + yc] - mean;
    const float LOG2PI = 1.8378770664093453f;
    nll_acc += 0.5f * (diff * diff / (std * std) + 2.0f * logf(std) + LOG2PI);
}
// heads unit: v in [0,16): m = v>>1, kp = v&1
__device__ __forceinline__ void heads_unit(SmemS* sm, int v, int tid) {
    int m = v >> 1, kp = v & 1;
    tile_gemm(sm, g_d2h, H_DIM, hw_hd, H_DIM, kp << 9, 512,
              m << 7, 0, M_FRAW64, nullptr, g_hp + kp * 65536, nullptr, 64, tid);
}

// ---------------- persistent kernel ----------------
__global__ __launch_bounds__(256, 1) void rnn_mma(
    const float* __restrict__ y,
    const float* __restrict__ dec_w1, const float* __restrict__ dec_b1,
    const float* __restrict__ dec_w2, const float* __restrict__ dec_b2,
    const float* __restrict__ mean_w, const float* __restrict__ mean_b,
    const float* __restrict__ std_w,  const float* __restrict__ std_b,
    const float* __restrict__ wih0,   const float* __restrict__ whh0,
    const float* __restrict__ bih0,   const float* __restrict__ bhh0,
    const float* __restrict__ wih1,   const float* __restrict__ whh1,
    const float* __restrict__ bih1,   const float* __restrict__ bhh1) {
    extern __shared__ char dynraw[];
    SmemS* sm = (SmemS*)dynraw;
    const int tid = threadIdx.x, bid = blockIdx.x, nb = gridDim.x;
    const int gs = nb * 256, gi = bid * 256 + tid;
    float nll_acc = 0.0f;

    // ---- one-time conversions ----
    for (int i = gi; i < H_DIM * R_DIM; i += gs) hw_d1[i] = __float2half(dec_w1[i]);
    for (int i = gi; i < H_DIM * H_DIM; i += gs) hw_d2[i] = __float2half(dec_w2[i]);
    for (int i = gi; i < 128 * H_DIM; i += gs) {
        int r = i >> 10, c = i & 1023;
        float v = (r < 32) ? mean_w[r * H_DIM + c] : (r < 64) ? std_w[(r - 32) * H_DIM + c] : 0.f;
        hw_hd[i] = __float2half(v);
    }
    for (int i = gi; i < R3 * YP; i += gs) {
        int r = i >> 6, c = i & 63;
        hw_i0[i] = (c < 32) ? __float2half(wih0[r * Y_DIM + c]) : __float2half(0.f);
    }
    for (int i = gi; i < R3 * R_DIM; i += gs) {
        hw_g0[i] = __float2half(whh0[i]);
        hw_i1[i] = __float2half(wih1[i]);
        hw_g1[i] = __float2half(whh1[i]);
    }
    for (int i = gi; i < B_SZ * R_DIM; i += gs) {
        g_h0[i] = 0.f; g_h1[i] = 0.f;
        g_h0h[i] = __float2half(0.f); g_h1h[i] = __float2half(0.f);
    }
    for (int i = gi; i < T_STEPS * B_SZ * YP; i += gs) {
        int c = i & 63, b = (i >> 6) & 1023, t = i >> 16;
        g_yh[i] = (c < 32) ? __float2half(y[(size_t)t * (B_SZ * Y_DIM) + b * 32 + c])
                           : __float2half(0.f);
    }
    unsigned int gen = 1;
    grid_sync(gen * nb);

    // ---- precompute GI0: 256 t x (8 m x 12 n), K = 64 ----
    for (int u = bid; u < T_STEPS * 96; u += nb) {
        int t = u / 96, v = u - t * 96;
        int m = v / 12, n = v - m * 12;
        tile_gemm(sm, g_yh + (size_t)t * (B_SZ * YP), YP, hw_i0, YP, 0, YP,
                  m << 7, n << 7, M_HBIAS, bih0,
                  nullptr, g_GI0 + (size_t)t * (B_SZ * R3), R3, tid);
    }
    gen++; grid_sync(gen * nb);

    for (int t = 0; t < T_STEPS; t++) {
        // P1: dec1(64) | GH0(96) | GH1(96) | heads(t-1)(16)
        int totA = 256 + ((t > 0) ? 16 : 0);
        for (int u = bid; u < totA; u += nb) {
            if (u < 64) {
                tile_gemm(sm, g_h1h, R_DIM, hw_d1, R_DIM, 0, R_DIM,
                          (u >> 3) << 7, (u & 7) << 7, M_HRELU, dec_b1,
                          nullptr, g_d1h, H_DIM, tid);
            } else if (u < 160) {
                int v = u - 64, m = v / 12, n = v - m * 12;
                tile_gemm(sm, g_h0h, R_DIM, hw_g0, R_DIM, 0, R_DIM,
                          m << 7, n << 7, M_FBIAS, bhh0, g_GH0, nullptr, R3, tid);
            } else if (u < 256) {
                int v = u - 160, m = v / 12, n = v - m * 12;
                tile_gemm(sm, g_h1h, R_DIM, hw_g1, R_DIM, 0, R_DIM,
                          m << 7, n << 7, M_FBIAS, bhh1, g_GH1, nullptr, R3, tid);
            } else {
                heads_unit(sm, u - 256, tid);
            }
        }
        gen++; grid_sync(gen * nb);

        // P2: dec2 full-K on blocks [0,64) | light work on blocks [64, nb)
        if (bid < 64) {
            tile_gemm(sm, g_d1h, H_DIM, hw_d2, H_DIM, 0, H_DIM,
                      (bid >> 3) << 7, (bid & 7) << 7, M_HRELU, dec_b2,
                      nullptr, g_d2h, H_DIM, tid);
        } else {
            int nlight = 2048 + ((t > 0) ? 128 : 0);
            for (int v = bid - 64; v < nlight; v += nb - 64) {
                if (v < 2048) gates0_chunk(t, v, tid);
                else nll_chunk(y, mean_b, std_b, t - 1, v - 2048, tid, nll_acc);
            }
        }
        gen++; grid_sync(gen * nb);

        // P3: GI1 (96 units)
        for (int u = bid; u < 96; u += nb) {
            int m = u / 12, n = u - m * 12;
            tile_gemm(sm, g_h0h, R_DIM, hw_i1, R_DIM, 0, R_DIM,
                      m << 7, n << 7, M_FBIAS, bih1, g_GI1, nullptr, R3, tid);
        }
        gen++; grid_sync(gen * nb);

        // P4: gates1 (2048 light)
        for (int u = bid; u < 2048; u += nb) gates1_chunk(u, tid);
        gen++; grid_sync(gen * nb);
    }

    // tail: heads for t = 255, then its NLL
    for (int u = bid; u < 16; u += nb) heads_unit(sm, u, tid);
    gen++; grid_sync(gen * nb);
    for (int u = bid; u < 128; u += nb) nll_chunk(y, mean_b, std_b, 255, u, tid, nll_acc);

#pragma unroll
    for (int o = 16; o > 0; o >>= 1) nll_acc += __shfl_xor_sync(0xffffffffu, nll_acc, o);
    if ((tid & 31) == 0) sm->red[tid >> 5] = nll_acc;
    __syncthreads();
    if (tid == 0) {
        float s = 0.f;
#pragma unroll
        for (int i = 0; i < 8; i++) s += sm->red[i];
        g_nllb[bid] = (double)s;
    }
}

__global__ void finalize_kernel(float* out, int nblocks) {
    double s = 0.0;
    for (int i = 0; i < nblocks; i++) s += g_nllb[i];
    out[0] = (float)s;
    g_bar = 0u;
}

extern "C" void kernel_launch(void* const* d_in, const int* in_sizes, int n_in,
                              void* d_out, int out_size) {
    const float* y      = (const float*)d_in[0];
    const float* dec_w1 = (const float*)d_in[1];
    const float* dec_b1 = (const float*)d_in[2];
    const float* dec_w2 = (const float*)d_in[3];
    const float* dec_b2 = (const float*)d_in[4];
    const float* mean_w = (const float*)d_in[5];
    const float* mean_b = (const float*)d_in[6];
    const float* std_w  = (const float*)d_in[7];
    const float* std_b  = (const float*)d_in[8];
    const float* wih0   = (const float*)d_in[9];
    const float* whh0   = (const float*)d_in[10];
    const float* bih0   = (const float*)d_in[11];
    const float* bhh0   = (const float*)d_in[12];
    const float* wih1   = (const float*)d_in[13];
    const float* whh1   = (const float*)d_in[14];
    const float* bih1   = (const float*)d_in[15];
    const float* bhh1   = (const float*)d_in[16];

    cudaFuncSetAttribute(rnn_mma, cudaFuncAttributeMaxDynamicSharedMemorySize,
                         (int)sizeof(SmemS));
    int dev = 0, nsm = 0;
    cudaGetDevice(&dev);
    cudaDeviceGetAttribute(&nsm, cudaDevAttrMultiProcessorCount, dev);
    if (nsm > 512) nsm = 512;

    rnn_mma<<<nsm, 256, sizeof(SmemS)>>>(y, dec_w1, dec_b1, dec_w2, dec_b2,
                                         mean_w, mean_b, std_w, std_b,
                                         wih0, whh0, bih0, bhh0,
                                         wih1, whh1, bih1, bhh1);
    finalize_kernel<<<1, 1>>>((float*)d_out, nsm);
}

// round 13
// speedup vs baseline: 1.2187x; 1.2187x over previous
#include <cuda_runtime.h>
#include <cuda_fp16.h>
#include <cstdint>
#include <math.h>

#define T_STEPS 256
#define B_SZ    1024
#define Y_DIM   32
#define H_DIM   1024
#define R_DIM   512
#define R3      1536
#define YP      64

// ---------------- device-global scratch ----------------
__device__ float  g_h0[B_SZ * R_DIM], g_h1[B_SZ * R_DIM];
__device__ __half g_h0h[B_SZ * R_DIM], g_h1h[B_SZ * R_DIM];
__device__ __half g_d1h[B_SZ * H_DIM], g_d2h[B_SZ * H_DIM];
__device__ float  g_pd1[2][B_SZ * H_DIM];
__device__ float  g_pd2[4][B_SZ * H_DIM];
__device__ float  g_pgh0[2][B_SZ * R3];
__device__ float  g_pgh1[2][B_SZ * R3];
__device__ float  g_pgi1[2][B_SZ * R3];
__device__ float  g_php[4][B_SZ * 64];
__device__ __half g_yh[T_STEPS * B_SZ * YP];
__device__ __half g_GI0[(size_t)T_STEPS * B_SZ * R3];
__device__ double g_nllb[512];
__device__ unsigned int g_bar;

__device__ __half hw_d1[H_DIM * R_DIM];
__device__ __half hw_d2[H_DIM * H_DIM];
__device__ __half hw_hd[128 * H_DIM];
__device__ __half hw_i0[R3 * YP];
__device__ __half hw_g0[R3 * R_DIM];
__device__ __half hw_i1[R3 * R_DIM];
__device__ __half hw_g1[R3 * R_DIM];

struct SmemS { char A[4][16384]; char B[4][16384]; float red[8]; };  // 128KB -> 1 CTA/SM
#define SWZ(o) ((o) ^ (((o) >> 3) & 0x70))

#define M_FRAW   0
#define M_FRAW64 1
#define M_HBIAS  2

// ---------------- helpers ----------------
__device__ __forceinline__ uint32_t smem_u32(const void* p) {
    uint32_t a;
    asm("{ .reg .u64 t; cvta.to.shared.u64 t, %1; cvt.u32.u64 %0, t; }" : "=r"(a) : "l"(p));
    return a;
}
__device__ __forceinline__ void cp16(uint32_t dst, const void* src) {
    asm volatile("cp.async.cg.shared.global [%0], [%1], 16;" :: "r"(dst), "l"(src));
}
__device__ __forceinline__ void ldsm4(uint32_t& r0, uint32_t& r1, uint32_t& r2,
                                      uint32_t& r3, uint32_t a) {
    asm volatile("ldmatrix.sync.aligned.m8n8.x4.shared.b16 {%0,%1,%2,%3}, [%4];"
                 : "=r"(r0), "=r"(r1), "=r"(r2), "=r"(r3) : "r"(a));
}
// fp32-accumulator mma (numerically proven in R6-R9)
__device__ __forceinline__ void mma16816(float* c, uint32_t a0, uint32_t a1,
                                         uint32_t a2, uint32_t a3,
                                         uint32_t b0, uint32_t b1) {
    asm volatile("mma.sync.aligned.m16n8k16.row.col.f32.f16.f16.f32 "
                 "{%0,%1,%2,%3}, {%4,%5,%6,%7}, {%8,%9}, {%0,%1,%2,%3};"
                 : "+f"(c[0]), "+f"(c[1]), "+f"(c[2]), "+f"(c[3])
                 : "r"(a0), "r"(a1), "r"(a2), "r"(a3), "r"(b0), "r"(b1));
}
__device__ __forceinline__ void grid_sync(unsigned int target) {
    __threadfence();
    __syncthreads();
    if (threadIdx.x == 0) {
        atomicAdd(&g_bar, 1u);
        while (*((volatile unsigned int*)&g_bar) < target) { __nanosleep(64); }
        __threadfence();
    }
    __syncthreads();
}
__device__ __forceinline__ float4 f4add(float4 a, float4 b) {
    return make_float4(a.x + b.x, a.y + b.y, a.z + b.z, a.w + b.w);
}
__device__ __forceinline__ float gru1(float ir, float iz, float in_,
                                      float hr, float hz, float hn, float h) {
    float r = 1.f / (1.f + expf(-(ir + hr)));
    float z = 1.f / (1.f + expf(-(iz + hz)));
    float nn = tanhf(in_ + r * hn);
    return (1.f - z) * nn + z * h;
}

// ---------------- chunk staging ----------------
__device__ __forceinline__ void stage_chunk(uint32_t dA, uint32_t dB,
                                            const __half* Ah, int ldA, int bm,
                                            const __half* Wh, int ldW, int k0, int tid) {
#pragma unroll
    for (int i = 0; i < 4; i++) {
        int e = tid + i * 256, r = e >> 3, q = e & 7;
        cp16(dA + SWZ(r * 128 + q * 16), Ah + (size_t)(bm + r) * ldA + k0 + q * 8);
        cp16(dB + SWZ(r * 128 + q * 16), Wh + (size_t)r * ldW + k0 + q * 8);
    }
    asm volatile("cp.async.commit_group;");
}

// ---------------- K-loop (fp32 acc, 4-stage pipeline) ----------------
__device__ void run_mma(SmemS* sm, const __half* Ah, int ldA,
                        const __half* Wh, int ldW, int kbase, int klen,
                        int bm, float acc[4][4][4], int tid) {
    uint32_t sA[4] = { smem_u32(sm->A[0]), smem_u32(sm->A[1]),
                       smem_u32(sm->A[2]), smem_u32(sm->A[3]) };
    uint32_t sB[4] = { smem_u32(sm->B[0]), smem_u32(sm->B[1]),
                       smem_u32(sm->B[2]), smem_u32(sm->B[3]) };
    const int lane = tid & 31, w = tid >> 5;
    const int wm = (w >> 2) * 64, wn = (w & 3) * 32;
    const int arow = lane & 15, acol = (lane >> 4) * 16;
    const int brow = (lane & 7) + ((lane & 16) ? 8 : 0);
    const int bcol = (lane & 8) ? 16 : 0;
#pragma unroll
    for (int mt = 0; mt < 4; mt++)
#pragma unroll
        for (int nt = 0; nt < 4; nt++)
#pragma unroll
            for (int i = 0; i < 4; i++) acc[mt][nt][i] = 0.f;

    const int nch = klen >> 6;
    const int pro = nch < 3 ? nch : 3;
    for (int s = 0; s < pro; s++)
        stage_chunk(sA[s], sB[s], Ah, ldA, bm, Wh, ldW, kbase + (s << 6), tid);
    int staged = pro;
    for (int kc = 0; kc < nch; kc++) {
        int pa = staged - kc - 1;
        if (pa >= 2)      asm volatile("cp.async.wait_group 2;");
        else if (pa == 1) asm volatile("cp.async.wait_group 1;");
        else              asm volatile("cp.async.wait_group 0;");
        __syncthreads();
        if (staged < nch) {
            int sb = staged & 3;
            stage_chunk(sA[sb], sB[sb], Ah, ldA, bm, Wh, ldW, kbase + (staged << 6), tid);
            staged++;
        }
        uint32_t aB = sA[kc & 3], bB = sB[kc & 3];
#pragma unroll
        for (int s = 0; s < 4; s++) {
            uint32_t b00, b01, b02, b03, b10, b11, b12, b13;
            ldsm4(b00, b01, b02, b03, bB + SWZ((wn + brow) * 128 + s * 32 + bcol));
            ldsm4(b10, b11, b12, b13, bB + SWZ((wn + 16 + brow) * 128 + s * 32 + bcol));
#pragma unroll
            for (int mt = 0; mt < 4; mt++) {
                uint32_t a0, a1, a2, a3;
                ldsm4(a0, a1, a2, a3, aB + SWZ((wm + mt * 16 + arow) * 128 + s * 32 + acol));
                mma16816(acc[mt][0], a0, a1, a2, a3, b00, b01);
                mma16816(acc[mt][1], a0, a1, a2, a3, b02, b03);
                mma16816(acc[mt][2], a0, a1, a2, a3, b10, b11);
                mma16816(acc[mt][3], a0, a1, a2, a3, b12, b13);
            }
        }
    }
}

// ---------------- epilogue ----------------
__device__ void tile_out(float acc[4][4][4], int mode, const float* bias,
                         float* Cf, __half* Ch, int ldC, int bm, int bn, int tid) {
    const int lane = tid & 31, w = tid >> 5;
    const int wm = (w >> 2) * 64, wn = (w & 3) * 32;
#pragma unroll
    for (int mt = 0; mt < 4; mt++)
#pragma unroll
        for (int nt = 0; nt < 4; nt++) {
            int row = bm + wm + mt * 16 + (lane >> 2);
            int lcol = wn + ((nt >> 1) << 4) + ((nt & 1) << 3) + 2 * (lane & 3);
            int col = bn + lcol;
            float x0 = acc[mt][nt][0], x1 = acc[mt][nt][1];
            float x2 = acc[mt][nt][2], x3 = acc[mt][nt][3];
            if (mode == M_FRAW) {
                *(float2*)(Cf + (size_t)row * ldC + col)       = make_float2(x0, x1);
                *(float2*)(Cf + (size_t)(row + 8) * ldC + col) = make_float2(x2, x3);
            } else if (mode == M_FRAW64) {
                // FIX (R10 bug): global batch row, NOT (row - bm) — g_php is a
                // full [B_SZ x 64] buffer shared by all heads m-tiles.
                if (lcol < 64) {
                    *(float2*)(Cf + (size_t)row * 64 + lcol)       = make_float2(x0, x1);
                    *(float2*)(Cf + (size_t)(row + 8) * 64 + lcol) = make_float2(x2, x3);
                }
            } else {  // M_HBIAS
                float b0 = bias[col], b1 = bias[col + 1];
                *(__half2*)(Ch + (size_t)row * ldC + col) =
                    __floats2half2_rn(x0 + b0, x1 + b1);
                *(__half2*)(Ch + (size_t)(row + 8) * ldC + col) =
                    __floats2half2_rn(x2 + b0, x3 + b1);
            }
        }
}

__device__ __forceinline__ void tile_gemm(SmemS* sm, const __half* Ah, int ldA,
                                          const __half* W, int ldW, int kbase, int klen,
                                          int bm, int bn, int mode, const float* bias,
                                          float* Cf, __half* Ch, int ldC, int tid) {
    float acc[4][4][4];
    run_mma(sm, Ah, ldA, W + (size_t)bn * ldW, ldW, kbase, klen, bm, acc, tid);
    tile_out(acc, mode, bias, Cf, Ch, ldC, bm, bn, tid);
}

// ---------------- light passes (float4 vectorized) ----------------
__device__ __forceinline__ void combine_d1(const float* dec_b1, int c, int tid) {
    int i = (c * 256 + tid) * 4, col = i & 1023;
    float4 x = f4add(f4add(*(const float4*)(g_pd1[0] + i), *(const float4*)(g_pd1[1] + i)),
                     *(const float4*)(dec_b1 + col));
    __half2 h01 = __floats2half2_rn(fmaxf(x.x, 0.f), fmaxf(x.y, 0.f));
    __half2 h23 = __floats2half2_rn(fmaxf(x.z, 0.f), fmaxf(x.w, 0.f));
    *(uint2*)(g_d1h + i) = make_uint2(*(uint32_t*)&h01, *(uint32_t*)&h23);
}
__device__ __forceinline__ void combine_d2(const float* dec_b2, int c, int tid) {
    int i = (c * 256 + tid) * 4, col = i & 1023;
    float4 x = f4add(f4add(*(const float4*)(g_pd2[0] + i), *(const float4*)(g_pd2[1] + i)),
             f4add(f4add(*(const float4*)(g_pd2[2] + i), *(const float4*)(g_pd2[3] + i)),
                   *(const float4*)(dec_b2 + col)));
    __half2 h01 = __floats2half2_rn(fmaxf(x.x, 0.f), fmaxf(x.y, 0.f));
    __half2 h23 = __floats2half2_rn(fmaxf(x.z, 0.f), fmaxf(x.w, 0.f));
    *(uint2*)(g_d2h + i) = make_uint2(*(uint32_t*)&h01, *(uint32_t*)&h23);
}
__device__ __forceinline__ void gates0v(const float* bhh0, int t, int c, int tid) {
    int i = (c * 256 + tid) * 4;
    int b = i >> 9, n = i & 511;
    size_t o = (size_t)b * R3 + n;
    const __half* gi = g_GI0 + (size_t)t * (B_SZ * R3) + o;
    uint2 ur = *(const uint2*)(gi);
    uint2 uz = *(const uint2*)(gi + 512);
    uint2 un = *(const uint2*)(gi + 1024);
    float2 ir01 = __half22float2(*(__half2*)&ur.x), ir23 = __half22float2(*(__half2*)&ur.y);
    float2 iz01 = __half22float2(*(__half2*)&uz.x), iz23 = __half22float2(*(__half2*)&uz.y);
    float2 in01 = __half22float2(*(__half2*)&un.x), in23 = __half22float2(*(__half2*)&un.y);
    float4 hr = f4add(f4add(*(const float4*)(g_pgh0[0] + o), *(const float4*)(g_pgh0[1] + o)),
                      *(const float4*)(bhh0 + n));
    float4 hz = f4add(f4add(*(const float4*)(g_pgh0[0] + o + 512), *(const float4*)(g_pgh0[1] + o + 512)),
                      *(const float4*)(bhh0 + n + 512));
    float4 hn = f4add(f4add(*(const float4*)(g_pgh0[0] + o + 1024), *(const float4*)(g_pgh0[1] + o + 1024)),
                      *(const float4*)(bhh0 + n + 1024));
    float4 h = *(const float4*)(g_h0 + i);
    float4 out;
    out.x = gru1(ir01.x, iz01.x, in01.x, hr.x, hz.x, hn.x, h.x);
    out.y = gru1(ir01.y, iz01.y, in01.y, hr.y, hz.y, hn.y, h.y);
    out.z = gru1(ir23.x, iz23.x, in23.x, hr.z, hz.z, hn.z, h.z);
    out.w = gru1(ir23.y, iz23.y, in23.y, hr.w, hz.w, hn.w, h.w);
    *(float4*)(g_h0 + i) = out;
    __half2 h01 = __floats2half2_rn(out.x, out.y), h23 = __floats2half2_rn(out.z, out.w);
    *(uint2*)(g_h0h + i) = make_uint2(*(uint32_t*)&h01, *(uint32_t*)&h23);
}
__device__ __forceinline__ void gates1v(const float* bih1, const float* bhh1,
                                        int c, int tid) {
    int i = (c * 256 + tid) * 4;
    int b = i >> 9, n = i & 511;
    size_t o = (size_t)b * R3 + n;
    float4 ir = f4add(f4add(*(const float4*)(g_pgi1[0] + o), *(const float4*)(g_pgi1[1] + o)),
                      *(const float4*)(bih1 + n));
    float4 iz = f4add(f4add(*(const float4*)(g_pgi1[0] + o + 512), *(const float4*)(g_pgi1[1] + o + 512)),
                      *(const float4*)(bih1 + n + 512));
    float4 in_ = f4add(f4add(*(const float4*)(g_pgi1[0] + o + 1024), *(const float4*)(g_pgi1[1] + o + 1024)),
                       *(const float4*)(bih1 + n + 1024));
    float4 hr = f4add(f4add(*(const float4*)(g_pgh1[0] + o), *(const float4*)(g_pgh1[1] + o)),
                      *(const float4*)(bhh1 + n));
    float4 hz = f4add(f4add(*(const float4*)(g_pgh1[0] + o + 512), *(const float4*)(g_pgh1[1] + o + 512)),
                      *(const float4*)(bhh1 + n + 512));
    float4 hn = f4add(f4add(*(const float4*)(g_pgh1[0] + o + 1024), *(const float4*)(g_pgh1[1] + o + 1024)),
                      *(const float4*)(bhh1 + n + 1024));
    float4 h = *(const float4*)(g_h1 + i);
    float4 out;
    out.x = gru1(ir.x, iz.x, in_.x, hr.x, hz.x, hn.x, h.x);
    out.y = gru1(ir.y, iz.y, in_.y, hr.y, hz.y, hn.y, h.y);
    out.z = gru1(ir.z, iz.z, in_.z, hr.z, hz.z, hn.z, h.z);
    out.w = gru1(ir.w, iz.w, in_.w, hr.w, hz.w, hn.w, h.w);
    *(float4*)(g_h1 + i) = out;
    __half2 h01 = __floats2half2_rn(out.x, out.y), h23 = __floats2half2_rn(out.z, out.w);
    *(uint2*)(g_h1h + i) = make_uint2(*(uint32_t*)&h01, *(uint32_t*)&h23);
}
__device__ __forceinline__ void nllv(const float* y, const float* mean_b,
                                     const float* std_b, int tt, int c, int tid,
                                     float& nll_acc) {
    int e = (c * 256 + tid) * 4;
    int b = e >> 5, yc = e & 31;
    int o = b * 64 + yc;
    float4 m = f4add(f4add(*(const float4*)(g_php[0] + o), *(const float4*)(g_php[1] + o)),
             f4add(f4add(*(const float4*)(g_php[2] + o), *(const float4*)(g_php[3] + o)),
                   *(const float4*)(mean_b + yc)));
    float4 s = f4add(f4add(*(const float4*)(g_php[0] + o + 32), *(const float4*)(g_php[1] + o + 32)),
             f4add(f4add(*(const float4*)(g_php[2] + o + 32), *(const float4*)(g_php[3] + o + 32)),
                   *(const float4*)(std_b + yc)));
    float4 yv = *(const float4*)(y + (size_t)tt * (B_SZ * Y_DIM) + b * 32 + yc);
    const float LOG2PI = 1.8378770664093453f;
    float sv[4] = {s.x, s.y, s.z, s.w};
    float mv[4] = {m.x, m.y, m.z, m.w};
    float yy[4] = {yv.x, yv.y, yv.z, yv.w};
#pragma unroll
    for (int j = 0; j < 4; j++) {
        float std = (sv[j] > 15.0f) ? sv[j] : log1pf(expf(sv[j]));
        float diff = yy[j] - mv[j];
        nll_acc += 0.5f * (diff * diff / (std * std) + 2.0f * logf(std) + LOG2PI);
    }
}

// ---------------- persistent kernel ----------------
__global__ __launch_bounds__(256, 1) void rnn_mma(
    const float* __restrict__ y,
    const float* __restrict__ dec_w1, const float* __restrict__ dec_b1,
    const float* __restrict__ dec_w2, const float* __restrict__ dec_b2,
    const float* __restrict__ mean_w, const float* __restrict__ mean_b,
    const float* __restrict__ std_w,  const float* __restrict__ std_b,
    const float* __restrict__ wih0,   const float* __restrict__ whh0,
    const float* __restrict__ bih0,   const float* __restrict__ bhh0,
    const float* __restrict__ wih1,   const float* __restrict__ whh1,
    const float* __restrict__ bih1,   const float* __restrict__ bhh1) {
    extern __shared__ char dynraw[];
    SmemS* sm = (SmemS*)dynraw;
    const int tid = threadIdx.x, bid = blockIdx.x, nb = gridDim.x;
    const int gs = nb * 256, gi = bid * 256 + tid;
    float nll_acc = 0.0f;

    // ---- one-time conversions ----
    for (int i = gi; i < H_DIM * R_DIM; i += gs) hw_d1[i] = __float2half(dec_w1[i]);
    for (int i = gi; i < H_DIM * H_DIM; i += gs) hw_d2[i] = __float2half(dec_w2[i]);
    for (int i = gi; i < 128 * H_DIM; i += gs) {
        int r = i >> 10, c = i & 1023;
        float v = (r < 32) ? mean_w[r * H_DIM + c] : (r < 64) ? std_w[(r - 32) * H_DIM + c] : 0.f;
        hw_hd[i] = __float2half(v);
    }
    for (int i = gi; i < R3 * YP; i += gs) {
        int r = i >> 6, c = i & 63;
        hw_i0[i] = (c < 32) ? __float2half(wih0[r * Y_DIM + c]) : __float2half(0.f);
    }
    for (int i = gi; i < R3 * R_DIM; i += gs) {
        hw_g0[i] = __float2half(whh0[i]);
        hw_i1[i] = __float2half(wih1[i]);
        hw_g1[i] = __float2half(whh1[i]);
    }
    for (int i = gi; i < B_SZ * R_DIM; i += gs) {
        g_h0[i] = 0.f; g_h1[i] = 0.f;
        g_h0h[i] = __float2half(0.f); g_h1h[i] = __float2half(0.f);
    }
    for (int i = gi; i < T_STEPS * B_SZ * YP; i += gs) {
        int c = i & 63, b = (i >> 6) & 1023, t = i >> 16;
        g_yh[i] = (c < 32) ? __float2half(y[(size_t)t * (B_SZ * Y_DIM) + b * 32 + c])
                           : __float2half(0.f);
    }
    unsigned int gen = 1;
    grid_sync(gen * nb);

    // ---- precompute GI0 (K=64, one chunk per tile) ----
    for (int u = bid; u < T_STEPS * 96; u += nb) {
        int t = u / 96, v = u - t * 96;
        int m = v / 12, n = v - m * 12;
        tile_gemm(sm, g_yh + (size_t)t * (B_SZ * YP), YP, hw_i0, YP, 0, YP,
                  m << 7, n << 7, M_HBIAS, bih0,
                  nullptr, g_GI0 + (size_t)t * (B_SZ * R3), R3, tid);
    }
    gen++; grid_sync(gen * nb);

    for (int t = 0; t < T_STEPS; t++) {
        // P1: dec1 ks2 (128) | GH0 ks2 (192) | GH1 ks2 (192) | heads(t-1) ks4 (32)
        int totP1 = 512 + ((t > 0) ? 32 : 0);
        for (int u = bid; u < totP1; u += nb) {
            if (u < 128) {
                int v = u >> 1, kp = u & 1;
                tile_gemm(sm, g_h1h, R_DIM, hw_d1, R_DIM, kp << 8, 256,
                          (v >> 3) << 7, (v & 7) << 7, M_FRAW, nullptr,
                          g_pd1[kp], nullptr, H_DIM, tid);
            } else if (u < 320) {
                int v = u - 128, vv = v >> 1, kp = v & 1;
                int m = vv / 12, n = vv - m * 12;
                tile_gemm(sm, g_h0h, R_DIM, hw_g0, R_DIM, kp << 8, 256,
                          m << 7, n << 7, M_FRAW, nullptr, g_pgh0[kp], nullptr, R3, tid);
            } else if (u < 512) {
                int v = u - 320, vv = v >> 1, kp = v & 1;
                int m = vv / 12, n = vv - m * 12;
                tile_gemm(sm, g_h1h, R_DIM, hw_g1, R_DIM, kp << 8, 256,
                          m << 7, n << 7, M_FRAW, nullptr, g_pgh1[kp], nullptr, R3, tid);
            } else {
                int v = u - 512, m = v >> 2, kp = v & 3;
                tile_gemm(sm, g_d2h, H_DIM, hw_hd, H_DIM, kp << 8, 256,
                          m << 7, 0, M_FRAW64, nullptr, g_php[kp], nullptr, 64, tid);
            }
        }
        gen++; grid_sync(gen * nb);

        // P2 (light): combine-d1 (1024) | gates0 (512) | nll(t-1) (32)
        int totP2 = 1536 + ((t > 0) ? 32 : 0);
        for (int u = bid; u < totP2; u += nb) {
            if (u < 1024) combine_d1(dec_b1, u, tid);
            else if (u < 1536) gates0v(bhh0, t, u - 1024, tid);
            else nllv(y, mean_b, std_b, t - 1, u - 1536, tid, nll_acc);
        }
        gen++; grid_sync(gen * nb);

        // P3: dec2 ks4 (256) | GI1 ks2 (192)
        for (int u = bid; u < 448; u += nb) {
            if (u < 256) {
                int v = u >> 2, kp = u & 3;
                tile_gemm(sm, g_d1h, H_DIM, hw_d2, H_DIM, kp << 8, 256,
                          (v >> 3) << 7, (v & 7) << 7, M_FRAW, nullptr,
                          g_pd2[kp], nullptr, H_DIM, tid);
            } else {
                int v = u - 256, vv = v >> 1, kp = v & 1;
                int m = vv / 12, n = vv - m * 12;
                tile_gemm(sm, g_h0h, R_DIM, hw_i1, R_DIM, kp << 8, 256,
                          m << 7, n << 7, M_FRAW, nullptr, g_pgi1[kp], nullptr, R3, tid);
            }
        }
        gen++; grid_sync(gen * nb);

        // P4 (light): combine-d2 (1024) | gates1 (512)
        for (int u = bid; u < 1536; u += nb) {
            if (u < 1024) combine_d2(dec_b2, u, tid);
            else gates1v(bih1, bhh1, u - 1024, tid);
        }
        gen++; grid_sync(gen * nb);
    }

    // tail: heads(255) + nll(255)
    for (int u = bid; u < 32; u += nb) {
        int m = u >> 2, kp = u & 3;
        tile_gemm(sm, g_d2h, H_DIM, hw_hd, H_DIM, kp << 8, 256,
                  m << 7, 0, M_FRAW64, nullptr, g_php[kp], nullptr, 64, tid);
    }
    gen++; grid_sync(gen * nb);
    for (int u = bid; u < 32; u += nb) nllv(y, mean_b, std_b, 255, u, tid, nll_acc);

#pragma unroll
    for (int o = 16; o > 0; o >>= 1) nll_acc += __shfl_xor_sync(0xffffffffu, nll_acc, o);
    if ((tid & 31) == 0) sm->red[tid >> 5] = nll_acc;
    __syncthreads();
    if (tid == 0) {
        float s = 0.f;
#pragma unroll
        for (int i = 0; i < 8; i++) s += sm->red[i];
        g_nllb[bid] = (double)s;
    }
}

__global__ void finalize_kernel(float* out, int nblocks) {
    double s = 0.0;
    for (int i = 0; i < nblocks; i++) s += g_nllb[i];
    out[0] = (float)s;
    g_bar = 0u;
}

extern "C" void kernel_launch(void* const* d_in, const int* in_sizes, int n_in,
                              void* d_out, int out_size) {
    const float* y      = (const float*)d_in[0];
    const float* dec_w1 = (const float*)d_in[1];
    const float* dec_b1 = (const float*)d_in[2];
    const float* dec_w2 = (const float*)d_in[3];
    const float* dec_b2 = (const float*)d_in[4];
    const float* mean_w = (const float*)d_in[5];
    const float* mean_b = (const float*)d_in[6];
    const float* std_w  = (const float*)d_in[7];
    const float* std_b  = (const float*)d_in[8];
    const float* wih0   = (const float*)d_in[9];
    const float* whh0   = (const float*)d_in[10];
    const float* bih0   = (const float*)d_in[11];
    const float* bhh0   = (const float*)d_in[12];
    const float* wih1   = (const float*)d_in[13];
    const float* whh1   = (const float*)d_in[14];
    const float* bih1   = (const float*)d_in[15];
    const float* bhh1   = (const float*)d_in[16];

    cudaFuncSetAttribute(rnn_mma, cudaFuncAttributeMaxDynamicSharedMemorySize,
                         (int)sizeof(SmemS));
    int dev = 0, nsm = 0;
    cudaGetDevice(&dev);
    cudaDeviceGetAttribute(&nsm, cudaDevAttrMultiProcessorCount, dev);
    if (nsm > 512) nsm = 512;

    rnn_mma<<<nsm, 256, sizeof(SmemS)>>>(y, dec_w1, dec_b1, dec_w2, dec_b2,
                                         mean_w, mean_b, std_w, std_b,
                                         wih0, whh0, bih0, bhh0,
                                         wih1, whh1, bih1, bhh1);
    finalize_kernel<<<1, 1>>>((float*)d_out, nsm);
}

// round 16
// speedup vs baseline: 1.2276x; 1.0073x over previous
#include <cuda_runtime.h>
#include <cuda_fp16.h>
#include <cstdint>
#include <math.h>

#define T_STEPS 256
#define B_SZ    1024
#define Y_DIM   32
#define H_DIM   1024
#define R_DIM   512
#define R3      1536
#define YP      64

// ---------------- device-global scratch ----------------
__device__ float  g_h0[B_SZ * R_DIM], g_h1[B_SZ * R_DIM];
__device__ __half g_h0h[B_SZ * R_DIM], g_h1h[B_SZ * R_DIM];
__device__ __half g_d1h[B_SZ * H_DIM], g_d2h[B_SZ * H_DIM];
__device__ float  g_GH0[B_SZ * R3], g_GH1[B_SZ * R3], g_GI1[B_SZ * R3];  // biased
__device__ float  g_php[B_SZ * 64];                 // heads mean|std (pre-bias)
__device__ __half g_yh[T_STEPS * B_SZ * YP];
__device__ __half g_GI0[(size_t)T_STEPS * B_SZ * R3];
__device__ double g_nllb[512];
__device__ unsigned int g_bar;

__device__ __half hw_d1[H_DIM * R_DIM];
__device__ __half hw_d2[H_DIM * H_DIM];
__device__ __half hw_hd[128 * H_DIM];
__device__ __half hw_i0[R3 * YP];
__device__ __half hw_g0[R3 * R_DIM];
__device__ __half hw_i1[R3 * R_DIM];
__device__ __half hw_g1[R3 * R_DIM];

struct SmemS { char A[4][16384]; char B[4][16384]; float red[8]; };  // 128KB -> 1 CTA/SM
#define SWZ(o) ((o) ^ (((o) >> 3) & 0x70))

#define M_HRELU  0   // half out, +bias, relu
#define M_FBIAS  1   // float out, +bias
#define M_HBIAS  2   // half out, +bias
#define M_FRAW64 3   // float raw, 64-wide, global batch row

// ---------------- helpers ----------------
__device__ __forceinline__ uint32_t smem_u32(const void* p) {
    uint32_t a;
    asm("{ .reg .u64 t; cvta.to.shared.u64 t, %1; cvt.u32.u64 %0, t; }" : "=r"(a) : "l"(p));
    return a;
}
__device__ __forceinline__ void cp16(uint32_t dst, const void* src) {
    asm volatile("cp.async.cg.shared.global [%0], [%1], 16;" :: "r"(dst), "l"(src));
}
__device__ __forceinline__ void ldsm4(uint32_t& r0, uint32_t& r1, uint32_t& r2,
                                      uint32_t& r3, uint32_t a) {
    asm volatile("ldmatrix.sync.aligned.m8n8.x4.shared.b16 {%0,%1,%2,%3}, [%4];"
                 : "=r"(r0), "=r"(r1), "=r"(r2), "=r"(r3) : "r"(a));
}
__device__ __forceinline__ void mma16816(float* c, uint32_t a0, uint32_t a1,
                                         uint32_t a2, uint32_t a3,
                                         uint32_t b0, uint32_t b1) {
    asm volatile("mma.sync.aligned.m16n8k16.row.col.f32.f16.f16.f32 "
                 "{%0,%1,%2,%3}, {%4,%5,%6,%7}, {%8,%9}, {%0,%1,%2,%3};"
                 : "+f"(c[0]), "+f"(c[1]), "+f"(c[2]), "+f"(c[3])
                 : "r"(a0), "r"(a1), "r"(a2), "r"(a3), "r"(b0), "r"(b1));
}
__device__ __forceinline__ void grid_sync(unsigned int target) {
    __threadfence();
    __syncthreads();
    if (threadIdx.x == 0) {
        atomicAdd(&g_bar, 1u);
        while (*((volatile unsigned int*)&g_bar) < target) { __nanosleep(64); }
        __threadfence();
    }
    __syncthreads();
}
__device__ __forceinline__ float4 f4add(float4 a, float4 b) {
    return make_float4(a.x + b.x, a.y + b.y, a.z + b.z, a.w + b.w);
}
__device__ __forceinline__ float gru1(float ir, float iz, float in_,
                                      float hr, float hz, float hn, float h) {
    float r = 1.f / (1.f + expf(-(ir + hr)));
    float z = 1.f / (1.f + expf(-(iz + hz)));
    float nn = tanhf(in_ + r * hn);
    return (1.f - z) * nn + z * h;
}

// ---------------- chunk staging ----------------
__device__ __forceinline__ void stage_chunk(uint32_t dA, uint32_t dB,
                                            const __half* Ah, int ldA, int bm,
                                            const __half* Wh, int ldW, int k0, int tid) {
#pragma unroll
    for (int i = 0; i < 4; i++) {
        int e = tid + i * 256, r = e >> 3, q = e & 7;
        cp16(dA + SWZ(r * 128 + q * 16), Ah + (size_t)(bm + r) * ldA + k0 + q * 8);
        cp16(dB + SWZ(r * 128 + q * 16), Wh + (size_t)r * ldW + k0 + q * 8);
    }
    asm volatile("cp.async.commit_group;");
}

// ---------------- K-loop (fp32 acc, 4-stage pipeline) ----------------
__device__ void run_mma(SmemS* sm, const __half* Ah, int ldA,
                        const __half* Wh, int ldW, int klen,
                        int bm, float acc[4][4][4], int tid) {
    uint32_t sA[4] = { smem_u32(sm->A[0]), smem_u32(sm->A[1]),
                       smem_u32(sm->A[2]), smem_u32(sm->A[3]) };
    uint32_t sB[4] = { smem_u32(sm->B[0]), smem_u32(sm->B[1]),
                       smem_u32(sm->B[2]), smem_u32(sm->B[3]) };
    const int lane = tid & 31, w = tid >> 5;
    const int wm = (w >> 2) * 64, wn = (w & 3) * 32;
    const int arow = lane & 15, acol = (lane >> 4) * 16;
    const int brow = (lane & 7) + ((lane & 16) ? 8 : 0);
    const int bcol = (lane & 8) ? 16 : 0;
#pragma unroll
    for (int mt = 0; mt < 4; mt++)
#pragma unroll
        for (int nt = 0; nt < 4; nt++)
#pragma unroll
            for (int i = 0; i < 4; i++) acc[mt][nt][i] = 0.f;

    const int nch = klen >> 6;
    const int pro = nch < 3 ? nch : 3;
    for (int s = 0; s < pro; s++)
        stage_chunk(sA[s], sB[s], Ah, ldA, bm, Wh, ldW, s << 6, tid);
    int staged = pro;
    for (int kc = 0; kc < nch; kc++) {
        int pa = staged - kc - 1;
        if (pa >= 2)      asm volatile("cp.async.wait_group 2;");
        else if (pa == 1) asm volatile("cp.async.wait_group 1;");
        else              asm volatile("cp.async.wait_group 0;");
        __syncthreads();
        if (staged < nch) {
            int sb = staged & 3;
            stage_chunk(sA[sb], sB[sb], Ah, ldA, bm, Wh, ldW, staged << 6, tid);
            staged++;
        }
        uint32_t aB = sA[kc & 3], bB = sB[kc & 3];
#pragma unroll
        for (int s = 0; s < 4; s++) {
            uint32_t b00, b01, b02, b03, b10, b11, b12, b13;
            ldsm4(b00, b01, b02, b03, bB + SWZ((wn + brow) * 128 + s * 32 + bcol));
            ldsm4(b10, b11, b12, b13, bB + SWZ((wn + 16 + brow) * 128 + s * 32 + bcol));
#pragma unroll
            for (int mt = 0; mt < 4; mt++) {
                uint32_t a0, a1, a2, a3;
                ldsm4(a0, a1, a2, a3, aB + SWZ((wm + mt * 16 + arow) * 128 + s * 32 + acol));
                mma16816(acc[mt][0], a0, a1, a2, a3, b00, b01);
                mma16816(acc[mt][1], a0, a1, a2, a3, b02, b03);
                mma16816(acc[mt][2], a0, a1, a2, a3, b10, b11);
                mma16816(acc[mt][3], a0, a1, a2, a3, b12, b13);
            }
        }
    }
}

// ---------------- epilogue ----------------
__device__ void tile_out(float acc[4][4][4], int mode, const float* bias,
                         float* Cf, __half* Ch, int ldC, int bm, int bn, int tid) {
    const int lane = tid & 31, w = tid >> 5;
    const int wm = (w >> 2) * 64, wn = (w & 3) * 32;
#pragma unroll
    for (int mt = 0; mt < 4; mt++)
#pragma unroll
        for (int nt = 0; nt < 4; nt++) {
            int row = bm + wm + mt * 16 + (lane >> 2);
            int lcol = wn + ((nt >> 1) << 4) + ((nt & 1) << 3) + 2 * (lane & 3);
            int col = bn + lcol;
            float x0 = acc[mt][nt][0], x1 = acc[mt][nt][1];
            float x2 = acc[mt][nt][2], x3 = acc[mt][nt][3];
            if (mode == M_FRAW64) {
                if (lcol < 64) {
                    *(float2*)(Cf + (size_t)row * 64 + lcol)       = make_float2(x0, x1);
                    *(float2*)(Cf + (size_t)(row + 8) * 64 + lcol) = make_float2(x2, x3);
                }
            } else {
                float b0 = bias[col], b1 = bias[col + 1];
                x0 += b0; x1 += b1; x2 += b0; x3 += b1;
                if (mode == M_FBIAS) {
                    *(float2*)(Cf + (size_t)row * ldC + col)       = make_float2(x0, x1);
                    *(float2*)(Cf + (size_t)(row + 8) * ldC + col) = make_float2(x2, x3);
                } else {
                    if (mode == M_HRELU) {
                        x0 = fmaxf(x0, 0.f); x1 = fmaxf(x1, 0.f);
                        x2 = fmaxf(x2, 0.f); x3 = fmaxf(x3, 0.f);
                    }
                    *(__half2*)(Ch + (size_t)row * ldC + col)       = __floats2half2_rn(x0, x1);
                    *(__half2*)(Ch + (size_t)(row + 8) * ldC + col) = __floats2half2_rn(x2, x3);
                }
            }
        }
}

__device__ __forceinline__ void tile_gemm(SmemS* sm, const __half* Ah, int ldA,
                                          const __half* W, int ldW, int klen,
                                          int bm, int bn, int mode, const float* bias,
                                          float* Cf, __half* Ch, int ldC, int tid) {
    float acc[4][4][4];
    run_mma(sm, Ah, ldA, W + (size_t)bn * ldW, ldW, klen, bm, acc, tid);
    tile_out(acc, mode, bias, Cf, Ch, ldC, bm, bn, tid);
}

// ---------------- light passes (float4 vectorized, biased buffers) ----------------
__device__ __forceinline__ void gates0v(int t, int c, int tid) {
    int i = (c * 256 + tid) * 4;
    int b = i >> 9, n = i & 511;
    size_t o = (size_t)b * R3 + n;
    const __half* gi = g_GI0 + (size_t)t * (B_SZ * R3) + o;
    uint2 ur = *(const uint2*)(gi);
    uint2 uz = *(const uint2*)(gi + 512);
    uint2 un = *(const uint2*)(gi + 1024);
    float2 ir01 = __half22float2(*(__half2*)&ur.x), ir23 = __half22float2(*(__half2*)&ur.y);
    float2 iz01 = __half22float2(*(__half2*)&uz.x), iz23 = __half22float2(*(__half2*)&uz.y);
    float2 in01 = __half22float2(*(__half2*)&un.x), in23 = __half22float2(*(__half2*)&un.y);
    float4 hr = *(const float4*)(g_GH0 + o);
    float4 hz = *(const float4*)(g_GH0 + o + 512);
    float4 hn = *(const float4*)(g_GH0 + o + 1024);
    float4 h = *(const float4*)(g_h0 + i);
    float4 out;
    out.x = gru1(ir01.x, iz01.x, in01.x, hr.x, hz.x, hn.x, h.x);
    out.y = gru1(ir01.y, iz01.y, in01.y, hr.y, hz.y, hn.y, h.y);
    out.z = gru1(ir23.x, iz23.x, in23.x, hr.z, hz.z, hn.z, h.z);
    out.w = gru1(ir23.y, iz23.y, in23.y, hr.w, hz.w, hn.w, h.w);
    *(float4*)(g_h0 + i) = out;
    __half2 h01 = __floats2half2_rn(out.x, out.y), h23 = __floats2half2_rn(out.z, out.w);
    *(uint2*)(g_h0h + i) = make_uint2(*(uint32_t*)&h01, *(uint32_t*)&h23);
}
__device__ __forceinline__ void gates1v(int c, int tid) {
    int i = (c * 256 + tid) * 4;
    int b = i >> 9, n = i & 511;
    size_t o = (size_t)b * R3 + n;
    float4 ir = *(const float4*)(g_GI1 + o);
    float4 iz = *(const float4*)(g_GI1 + o + 512);
    float4 in_ = *(const float4*)(g_GI1 + o + 1024);
    float4 hr = *(const float4*)(g_GH1 + o);
    float4 hz = *(const float4*)(g_GH1 + o + 512);
    float4 hn = *(const float4*)(g_GH1 + o + 1024);
    float4 h = *(const float4*)(g_h1 + i);
    float4 out;
    out.x = gru1(ir.x, iz.x, in_.x, hr.x, hz.x, hn.x, h.x);
    out.y = gru1(ir.y, iz.y, in_.y, hr.y, hz.y, hn.y, h.y);
    out.z = gru1(ir.z, iz.z, in_.z, hr.z, hz.z, hn.z, h.z);
    out.w = gru1(ir.w, iz.w, in_.w, hr.w, hz.w, hn.w, h.w);
    *(float4*)(g_h1 + i) = out;
    __half2 h01 = __floats2half2_rn(out.x, out.y), h23 = __floats2half2_rn(out.z, out.w);
    *(uint2*)(g_h1h + i) = make_uint2(*(uint32_t*)&h01, *(uint32_t*)&h23);
}
__device__ __forceinline__ void nllv(const float* y, const float* mean_b,
                                     const float* std_b, int tt, int c, int tid,
                                     float& nll_acc) {
    int e = (c * 256 + tid) * 4;
    int b = e >> 5, yc = e & 31;
    int o = b * 64 + yc;
    float4 m = f4add(*(const float4*)(g_php + o), *(const float4*)(mean_b + yc));
    float4 s = f4add(*(const float4*)(g_php + o + 32), *(const float4*)(std_b + yc));
    float4 yv = *(const float4*)(y + (size_t)tt * (B_SZ * Y_DIM) + b * 32 + yc);
    const float LOG2PI = 1.8378770664093453f;
    float sv[4] = {s.x, s.y, s.z, s.w};
    float mv[4] = {m.x, m.y, m.z, m.w};
    float yy[4] = {yv.x, yv.y, yv.z, yv.w};
#pragma unroll
    for (int j = 0; j < 4; j++) {
        float std = (sv[j] > 15.0f) ? sv[j] : log1pf(expf(sv[j]));
        float diff = yy[j] - mv[j];
        nll_acc += 0.5f * (diff * diff / (std * std) + 2.0f * logf(std) + LOG2PI);
    }
}

// P1 GEMM unit dispatch (v in [0,256)): dec1 | GH0 | GH1, all full-K direct-write
__device__ __forceinline__ void p1_unit(SmemS* sm, int v,
                                        const float* dec_b1, const float* bhh0,
                                        const float* bhh1, int tid) {
    if (v < 64) {
        tile_gemm(sm, g_h1h, R_DIM, hw_d1, R_DIM, R_DIM,
                  (v >> 3) << 7, (v & 7) << 7, M_HRELU, dec_b1,
                  nullptr, g_d1h, H_DIM, tid);
    } else if (v < 160) {
        int w = v - 64, m = w / 12, n = w - m * 12;
        tile_gemm(sm, g_h0h, R_DIM, hw_g0, R_DIM, R_DIM,
                  m << 7, n << 7, M_FBIAS, bhh0, g_GH0, nullptr, R3, tid);
    } else {
        int w = v - 160, m = w / 12, n = w - m * 12;
        tile_gemm(sm, g_h1h, R_DIM, hw_g1, R_DIM, R_DIM,
                  m << 7, n << 7, M_FBIAS, bhh1, g_GH1, nullptr, R3, tid);
    }
}
__device__ __forceinline__ void heads_unit(SmemS* sm, int m, int tid) {
    tile_gemm(sm, g_d2h, H_DIM, hw_hd, H_DIM, H_DIM,
              m << 7, 0, M_FRAW64, nullptr, g_php, nullptr, 64, tid);
}

// ---------------- persistent kernel ----------------
__global__ __launch_bounds__(256, 1) void rnn_mma(
    const float* __restrict__ y,
    const float* __restrict__ dec_w1, const float* __restrict__ dec_b1,
    const float* __restrict__ dec_w2, const float* __restrict__ dec_b2,
    const float* __restrict__ mean_w, const float* __restrict__ mean_b,
    const float* __restrict__ std_w,  const float* __restrict__ std_b,
    const float* __restrict__ wih0,   const float* __restrict__ whh0,
    const float* __restrict__ bih0,   const float* __restrict__ bhh0,
    const float* __restrict__ wih1,   const float* __restrict__ whh1,
    const float* __restrict__ bih1,   const float* __restrict__ bhh1) {
    extern __shared__ char dynraw[];
    SmemS* sm = (SmemS*)dynraw;
    const int tid = threadIdx.x, bid = blockIdx.x, nb = gridDim.x;
    const int gs = nb * 256, gi = bid * 256 + tid;
    float nll_acc = 0.0f;

    // ---- one-time conversions ----
    for (int i = gi; i < H_DIM * R_DIM; i += gs) hw_d1[i] = __float2half(dec_w1[i]);
    for (int i = gi; i < H_DIM * H_DIM; i += gs) hw_d2[i] = __float2half(dec_w2[i]);
    for (int i = gi; i < 128 * H_DIM; i += gs) {
        int r = i >> 10, c = i & 1023;
        float v = (r < 32) ? mean_w[r * H_DIM + c] : (r < 64) ? std_w[(r - 32) * H_DIM + c] : 0.f;
        hw_hd[i] = __float2half(v);
    }
    for (int i = gi; i < R3 * YP; i += gs) {
        int r = i >> 6, c = i & 63;
        hw_i0[i] = (c < 32) ? __float2half(wih0[r * Y_DIM + c]) : __float2half(0.f);
    }
    for (int i = gi; i < R3 * R_DIM; i += gs) {
        hw_g0[i] = __float2half(whh0[i]);
        hw_i1[i] = __float2half(wih1[i]);
        hw_g1[i] = __float2half(whh1[i]);
    }
    for (int i = gi; i < B_SZ * R_DIM; i += gs) {
        g_h0[i] = 0.f; g_h1[i] = 0.f;
        g_h0h[i] = __float2half(0.f); g_h1h[i] = __float2half(0.f);
    }
    for (int i = gi; i < T_STEPS * B_SZ * YP; i += gs) {
        int c = i & 63, b = (i >> 6) & 1023, t = i >> 16;
        g_yh[i] = (c < 32) ? __float2half(y[(size_t)t * (B_SZ * Y_DIM) + b * 32 + c])
                           : __float2half(0.f);
    }
    unsigned int gen = 1;
    grid_sync(gen * nb);

    // ---- precompute GI0 (K=64, one chunk per tile) ----
    for (int u = bid; u < T_STEPS * 96; u += nb) {
        int t = u / 96, v = u - t * 96;
        int m = v / 12, n = v - m * 12;
        tile_gemm(sm, g_yh + (size_t)t * (B_SZ * YP), YP, hw_i0, YP, YP,
                  m << 7, n << 7, M_HBIAS, bih0,
                  nullptr, g_GI0 + (size_t)t * (B_SZ * R3), R3, tid);
    }
    gen++; grid_sync(gen * nb);

    for (int t = 0; t < T_STEPS; t++) {
        // P1: dec1(64) | GH0(96) | GH1(96) full-K + heads(t-1) (8 x 16-chunk units
        // placed at slots [116,124) so they land on single-unit blocks)
        if (t > 0) {
            for (int u = bid; u < 264; u += nb) {
                if (u >= 116 && u < 124) heads_unit(sm, u - 116, tid);
                else p1_unit(sm, (u < 116) ? u : u - 8, dec_b1, bhh0, bhh1, tid);
            }
        } else {
            for (int u = bid; u < 256; u += nb) p1_unit(sm, u, dec_b1, bhh0, bhh1, tid);
        }
        gen++; grid_sync(gen * nb);

        // P2 (light): gates0 (512) | nll(t-1) (32)
        int totP2 = 512 + ((t > 0) ? 32 : 0);
        for (int u = bid; u < totP2; u += nb) {
            if (u < 512) gates0v(t, u, tid);
            else nllv(y, mean_b, std_b, t - 1, u - 512, tid, nll_acc);
        }
        gen++; grid_sync(gen * nb);

        // P3: blocks [0,64): dec2 full-K (16 chunks, direct d2h);
        //     blocks [64,nb): GI1 full-K (96 units, 8 chunks, direct biased)
        if (bid < 64) {
            tile_gemm(sm, g_d1h, H_DIM, hw_d2, H_DIM, H_DIM,
                      (bid >> 3) << 7, (bid & 7) << 7, M_HRELU, dec_b2,
                      nullptr, g_d2h, H_DIM, tid);
        } else {
            for (int u = bid - 64; u < 96; u += nb - 64) {
                int m = u / 12, n = u - m * 12;
                tile_gemm(sm, g_h0h, R_DIM, hw_i1, R_DIM, R_DIM,
                          m << 7, n << 7, M_FBIAS, bih1, g_GI1, nullptr, R3, tid);
            }
        }
        gen++; grid_sync(gen * nb);

        // P4 (light): gates1 (512)
        for (int u = bid; u < 512; u += nb) gates1v(u, tid);
        gen++; grid_sync(gen * nb);
    }

    // tail: heads(255) + nll(255)
    for (int u = bid; u < 8; u += nb) heads_unit(sm, u, tid);
    gen++; grid_sync(gen * nb);
    for (int u = bid; u < 32; u += nb) nllv(y, mean_b, std_b, 255, u, tid, nll_acc);

#pragma unroll
    for (int o = 16; o > 0; o >>= 1) nll_acc += __shfl_xor_sync(0xffffffffu, nll_acc, o);
    if ((tid & 31) == 0) sm->red[tid >> 5] = nll_acc;
    __syncthreads();
    if (tid == 0) {
        float s = 0.f;
#pragma unroll
        for (int i = 0; i < 8; i++) s += sm->red[i];
        g_nllb[bid] = (double)s;
    }
}

__global__ void finalize_kernel(float* out, int nblocks) {
    double s = 0.0;
    for (int i = 0; i < nblocks; i++) s += g_nllb[i];
    out[0] = (float)s;
    g_bar = 0u;
}

extern "C" void kernel_launch(void* const* d_in, const int* in_sizes, int n_in,
                              void* d_out, int out_size) {
    const float* y      = (const float*)d_in[0];
    const float* dec_w1 = (const float*)d_in[1];
    const float* dec_b1 = (const float*)d_in[2];
    const float* dec_w2 = (const float*)d_in[3];
    const float* dec_b2 = (const float*)d_in[4];
    const float* mean_w = (const float*)d_in[5];
    const float* mean_b = (const float*)d_in[6];
    const float* std_w  = (const float*)d_in[7];
    const float* std_b  = (const float*)d_in[8];
    const float* wih0   = (const float*)d_in[9];
    const float* whh0   = (const float*)d_in[10];
    const float* bih0   = (const float*)d_in[11];
    const float* bhh0   = (const float*)d_in[12];
    const float* wih1   = (const float*)d_in[13];
    const float* whh1   = (const float*)d_in[14];
    const float* bih1   = (const float*)d_in[15];
    const float* bhh1   = (const float*)d_in[16];

    cudaFuncSetAttribute(rnn_mma, cudaFuncAttributeMaxDynamicSharedMemorySize,
                         (int)sizeof(SmemS));
    int dev = 0, nsm = 0;
    cudaGetDevice(&dev);
    cudaDeviceGetAttribute(&nsm, cudaDevAttrMultiProcessorCount, dev);
    if (nsm > 512) nsm = 512;

    rnn_mma<<<nsm, 256, sizeof(SmemS)>>>(y, dec_w1, dec_b1, dec_w2, dec_b2,
                                         mean_w, mean_b, std_w, std_b,
                                         wih0, whh0, bih0, bhh0,
                                         wih1, whh1, bih1, bhh1);
    finalize_kernel<<<1, 1>>>((float*)d_out, nsm);
}

// round 17
// speedup vs baseline: 1.4644x; 1.1929x over previous
#include <cuda_runtime.h>
#include <cuda_fp16.h>
#include <cstdint>
#include <math.h>

#define T_STEPS 256
#define B_SZ    1024
#define Y_DIM   32
#define H_DIM   1024
#define R_DIM   512
#define R3      1536
#define YP      64

// ---------------- device-global scratch ----------------
__device__ float  g_h0[B_SZ * R_DIM], g_h1[B_SZ * R_DIM];
__device__ __half g_h0h[B_SZ * R_DIM], g_h1h[B_SZ * R_DIM];
__device__ __half g_d1h[B_SZ * H_DIM], g_d2h[B_SZ * H_DIM];
__device__ float  g_GH0[B_SZ * R3], g_GH1[B_SZ * R3], g_GI1[B_SZ * R3];  // biased
__device__ float  g_php[B_SZ * 64];
__device__ __half g_yh[T_STEPS * B_SZ * YP];
__device__ __half g_GI0[(size_t)T_STEPS * B_SZ * R3];
__device__ double g_nllb[512];
__device__ unsigned int g_bar;

__device__ __half hw_d1[H_DIM * R_DIM];
__device__ __half hw_d2[H_DIM * H_DIM];
__device__ __half hw_hd[128 * H_DIM];
__device__ __half hw_i0[R3 * YP];
__device__ __half hw_g0[R3 * R_DIM];
__device__ __half hw_i1[R3 * R_DIM];
__device__ __half hw_g1[R3 * R_DIM];

// 3-buffer mega-chunk ring: each mega = 128 K-cols = two 64-col subs (16KB each)
struct SmemS { char A[3][32768]; char B[3][32768]; float red[8]; };  // ~196KB -> 1 CTA/SM
#define SWZ(o) ((o) ^ (((o) >> 3) & 0x70))

#define M_HRELU  0
#define M_FBIAS  1
#define M_HBIAS  2
#define M_FRAW64 3

// ---------------- helpers ----------------
__device__ __forceinline__ uint32_t smem_u32(const void* p) {
    uint32_t a;
    asm("{ .reg .u64 t; cvta.to.shared.u64 t, %1; cvt.u32.u64 %0, t; }" : "=r"(a) : "l"(p));
    return a;
}
__device__ __forceinline__ void cp16(uint32_t dst, const void* src) {
    asm volatile("cp.async.cg.shared.global [%0], [%1], 16;" :: "r"(dst), "l"(src));
}
__device__ __forceinline__ void ldsm4(uint32_t& r0, uint32_t& r1, uint32_t& r2,
                                      uint32_t& r3, uint32_t a) {
    asm volatile("ldmatrix.sync.aligned.m8n8.x4.shared.b16 {%0,%1,%2,%3}, [%4];"
                 : "=r"(r0), "=r"(r1), "=r"(r2), "=r"(r3) : "r"(a));
}
__device__ __forceinline__ void mma16816(float* c, uint32_t a0, uint32_t a1,
                                         uint32_t a2, uint32_t a3,
                                         uint32_t b0, uint32_t b1) {
    asm volatile("mma.sync.aligned.m16n8k16.row.col.f32.f16.f16.f32 "
                 "{%0,%1,%2,%3}, {%4,%5,%6,%7}, {%8,%9}, {%0,%1,%2,%3};"
                 : "+f"(c[0]), "+f"(c[1]), "+f"(c[2]), "+f"(c[3])
                 : "r"(a0), "r"(a1), "r"(a2), "r"(a3), "r"(b0), "r"(b1));
}
// Cheap grid barrier: bar.sync orders block writes before thread0's release-red
// (cumulative release); spinners use acquire loads. No per-thread MEMBAR.GPU,
// no same-address RMW return path.
__device__ __forceinline__ void grid_sync(unsigned int target) {
    __syncthreads();
    if (threadIdx.x == 0) {
        asm volatile("red.release.gpu.global.add.u32 [%0], 1;"
                     :: "l"(&g_bar) : "memory");
        unsigned int v;
        while (1) {
            asm volatile("ld.acquire.gpu.global.u32 %0, [%1];"
                         : "=r"(v) : "l"(&g_bar) : "memory");
            if ((int)(v - target) >= 0) break;
            __nanosleep(32);
        }
    }
    __syncthreads();
}
__device__ __forceinline__ float4 f4add(float4 a, float4 b) {
    return make_float4(a.x + b.x, a.y + b.y, a.z + b.z, a.w + b.w);
}
__device__ __forceinline__ float gru1(float ir, float iz, float in_,
                                      float hr, float hz, float hn, float h) {
    float r = 1.f / (1.f + expf(-(ir + hr)));
    float z = 1.f / (1.f + expf(-(iz + hz)));
    float nn = tanhf(in_ + r * hn);
    return (1.f - z) * nn + z * h;
}

// ---------------- staging: one 64-col sub (A 128x64h + B 128x64h) ----------------
__device__ __forceinline__ void stage_sub(uint32_t dA, uint32_t dB,
                                          const __half* Ah, int ldA, int bm,
                                          const __half* Wh, int ldW, int k0, int tid) {
#pragma unroll
    for (int i = 0; i < 4; i++) {
        int e = tid + i * 256, r = e >> 3, q = e & 7;
        cp16(dA + SWZ(r * 128 + q * 16), Ah + (size_t)(bm + r) * ldA + k0 + q * 8);
        cp16(dB + SWZ(r * 128 + q * 16), Wh + (size_t)r * ldW + k0 + q * 8);
    }
}
// one mega = up to 2 subs, single commit group
__device__ __forceinline__ void stage_mega(uint32_t aB, uint32_t bB,
                                           const __half* Ah, int ldA, int bm,
                                           const __half* Wh, int ldW, int k0,
                                           int nsub, int tid) {
    stage_sub(aB, bB, Ah, ldA, bm, Wh, ldW, k0, tid);
    if (nsub > 1) stage_sub(aB + 16384, bB + 16384, Ah, ldA, bm, Wh, ldW, k0 + 64, tid);
    asm volatile("cp.async.commit_group;");
}

// ---------------- K-loop: 3-mega ring, ONE wait+sync per 128 K ----------------
__device__ void run_mma(SmemS* sm, const __half* Ah, int ldA,
                        const __half* Wh, int ldW, int klen,
                        int bm, float acc[4][4][4], int tid) {
    uint32_t sA[3] = { smem_u32(sm->A[0]), smem_u32(sm->A[1]), smem_u32(sm->A[2]) };
    uint32_t sB[3] = { smem_u32(sm->B[0]), smem_u32(sm->B[1]), smem_u32(sm->B[2]) };
    const int lane = tid & 31, w = tid >> 5;
    const int wm = (w >> 2) * 64, wn = (w & 3) * 32;
    const int arow = lane & 15, acol = (lane >> 4) * 16;
    const int brow = (lane & 7) + ((lane & 16) ? 8 : 0);
    const int bcol = (lane & 8) ? 16 : 0;
#pragma unroll
    for (int mt = 0; mt < 4; mt++)
#pragma unroll
        for (int nt = 0; nt < 4; nt++)
#pragma unroll
            for (int i = 0; i < 4; i++) acc[mt][nt][i] = 0.f;

    const int nchS = klen >> 6;            // 64-col subs
    const int nmg = (nchS + 1) >> 1;       // 128-col megas
    int staged = 0;
    // prologue: stage up to 2 megas
    for (; staged < 2 && staged < nmg; staged++) {
        int k0 = staged << 7;
        int ns = (nchS - (staged << 1) >= 2) ? 2 : 1;
        stage_mega(sA[staged], sB[staged], Ah, ldA, bm, Wh, ldW, k0, ns, tid);
    }
    for (int mg = 0; mg < nmg; mg++) {
        int pa = staged - (mg + 1);
        if (pa >= 2)      asm volatile("cp.async.wait_group 2;");
        else if (pa == 1) asm volatile("cp.async.wait_group 1;");
        else              asm volatile("cp.async.wait_group 0;");
        __syncthreads();   // buffer mg ready; all warps done with buffer (mg+2)%3
        if (staged < nmg) {
            int b = staged % 3;
            int k0 = staged << 7;
            int ns = (nchS - (staged << 1) >= 2) ? 2 : 1;
            stage_mega(sA[b], sB[b], Ah, ldA, bm, Wh, ldW, k0, ns, tid);
            staged++;
        }
        const int buf = mg % 3;
        const int nsub = (nchS - (mg << 1) >= 2) ? 2 : 1;
#pragma unroll 1
        for (int sub = 0; sub < nsub; sub++) {
            uint32_t aB = sA[buf] + sub * 16384, bB = sB[buf] + sub * 16384;
#pragma unroll
            for (int s = 0; s < 4; s++) {
                uint32_t b00, b01, b02, b03, b10, b11, b12, b13;
                ldsm4(b00, b01, b02, b03, bB + SWZ((wn + brow) * 128 + s * 32 + bcol));
                ldsm4(b10, b11, b12, b13, bB + SWZ((wn + 16 + brow) * 128 + s * 32 + bcol));
#pragma unroll
                for (int mt = 0; mt < 4; mt++) {
                    uint32_t a0, a1, a2, a3;
                    ldsm4(a0, a1, a2, a3,
                          aB + SWZ((wm + mt * 16 + arow) * 128 + s * 32 + acol));
                    mma16816(acc[mt][0], a0, a1, a2, a3, b00, b01);
                    mma16816(acc[mt][1], a0, a1, a2, a3, b02, b03);
                    mma16816(acc[mt][2], a0, a1, a2, a3, b10, b11);
                    mma16816(acc[mt][3], a0, a1, a2, a3, b12, b13);
                }
            }
        }
    }
}

// ---------------- epilogue ----------------
__device__ void tile_out(float acc[4][4][4], int mode, const float* bias,
                         float* Cf, __half* Ch, int ldC, int bm, int bn, int tid) {
    const int lane = tid & 31, w = tid >> 5;
    const int wm = (w >> 2) * 64, wn = (w & 3) * 32;
#pragma unroll
    for (int mt = 0; mt < 4; mt++)
#pragma unroll
        for (int nt = 0; nt < 4; nt++) {
            int row = bm + wm + mt * 16 + (lane >> 2);
            int lcol = wn + ((nt >> 1) << 4) + ((nt & 1) << 3) + 2 * (lane & 3);
            int col = bn + lcol;
            float x0 = acc[mt][nt][0], x1 = acc[mt][nt][1];
            float x2 = acc[mt][nt][2], x3 = acc[mt][nt][3];
            if (mode == M_FRAW64) {
                if (lcol < 64) {
                    *(float2*)(Cf + (size_t)row * 64 + lcol)       = make_float2(x0, x1);
                    *(float2*)(Cf + (size_t)(row + 8) * 64 + lcol) = make_float2(x2, x3);
                }
            } else {
                float b0 = bias[col], b1 = bias[col + 1];
                x0 += b0; x1 += b1; x2 += b0; x3 += b1;
                if (mode == M_FBIAS) {
                    *(float2*)(Cf + (size_t)row * ldC + col)       = make_float2(x0, x1);
                    *(float2*)(Cf + (size_t)(row + 8) * ldC + col) = make_float2(x2, x3);
                } else {
                    if (mode == M_HRELU) {
                        x0 = fmaxf(x0, 0.f); x1 = fmaxf(x1, 0.f);
                        x2 = fmaxf(x2, 0.f); x3 = fmaxf(x3, 0.f);
                    }
                    *(__half2*)(Ch + (size_t)row * ldC + col)       = __floats2half2_rn(x0, x1);
                    *(__half2*)(Ch + (size_t)(row + 8) * ldC + col) = __floats2half2_rn(x2, x3);
                }
            }
        }
}

__device__ __forceinline__ void tile_gemm(SmemS* sm, const __half* Ah, int ldA,
                                          const __half* W, int ldW, int klen,
                                          int bm, int bn, int mode, const float* bias,
                                          float* Cf, __half* Ch, int ldC, int tid) {
    float acc[4][4][4];
    run_mma(sm, Ah, ldA, W + (size_t)bn * ldW, ldW, klen, bm, acc, tid);
    tile_out(acc, mode, bias, Cf, Ch, ldC, bm, bn, tid);
}

// ---------------- light passes ----------------
__device__ __forceinline__ void gates0v(int t, int c, int tid) {
    int i = (c * 256 + tid) * 4;
    int b = i >> 9, n = i & 511;
    size_t o = (size_t)b * R3 + n;
    const __half* gi = g_GI0 + (size_t)t * (B_SZ * R3) + o;
    uint2 ur = *(const uint2*)(gi);
    uint2 uz = *(const uint2*)(gi + 512);
    uint2 un = *(const uint2*)(gi + 1024);
    float2 ir01 = __half22float2(*(__half2*)&ur.x), ir23 = __half22float2(*(__half2*)&ur.y);
    float2 iz01 = __half22float2(*(__half2*)&uz.x), iz23 = __half22float2(*(__half2*)&uz.y);
    float2 in01 = __half22float2(*(__half2*)&un.x), in23 = __half22float2(*(__half2*)&un.y);
    float4 hr = *(const float4*)(g_GH0 + o);
    float4 hz = *(const float4*)(g_GH0 + o + 512);
    float4 hn = *(const float4*)(g_GH0 + o + 1024);
    float4 h = *(const float4*)(g_h0 + i);
    float4 out;
    out.x = gru1(ir01.x, iz01.x, in01.x, hr.x, hz.x, hn.x, h.x);
    out.y = gru1(ir01.y, iz01.y, in01.y, hr.y, hz.y, hn.y, h.y);
    out.z = gru1(ir23.x, iz23.x, in23.x, hr.z, hz.z, hn.z, h.z);
    out.w = gru1(ir23.y, iz23.y, in23.y, hr.w, hz.w, hn.w, h.w);
    *(float4*)(g_h0 + i) = out;
    __half2 h01 = __floats2half2_rn(out.x, out.y), h23 = __floats2half2_rn(out.z, out.w);
    *(uint2*)(g_h0h + i) = make_uint2(*(uint32_t*)&h01, *(uint32_t*)&h23);
}
__device__ __forceinline__ void gates1v(int c, int tid) {
    int i = (c * 256 + tid) * 4;
    int b = i >> 9, n = i & 511;
    size_t o = (size_t)b * R3 + n;
    float4 ir = *(const float4*)(g_GI1 + o);
    float4 iz = *(const float4*)(g_GI1 + o + 512);
    float4 in_ = *(const float4*)(g_GI1 + o + 1024);
    float4 hr = *(const float4*)(g_GH1 + o);
    float4 hz = *(const float4*)(g_GH1 + o + 512);
    float4 hn = *(const float4*)(g_GH1 + o + 1024);
    float4 h = *(const float4*)(g_h1 + i);
    float4 out;
    out.x = gru1(ir.x, iz.x, in_.x, hr.x, hz.x, hn.x, h.x);
    out.y = gru1(ir.y, iz.y, in_.y, hr.y, hz.y, hn.y, h.y);
    out.z = gru1(ir.z, iz.z, in_.z, hr.z, hz.z, hn.z, h.z);
    out.w = gru1(ir.w, iz.w, in_.w, hr.w, hz.w, hn.w, h.w);
    *(float4*)(g_h1 + i) = out;
    __half2 h01 = __floats2half2_rn(out.x, out.y), h23 = __floats2half2_rn(out.z, out.w);
    *(uint2*)(g_h1h + i) = make_uint2(*(uint32_t*)&h01, *(uint32_t*)&h23);
}
__device__ __forceinline__ void nllv(const float* y, const float* mean_b,
                                     const float* std_b, int tt, int c, int tid,
                                     float& nll_acc) {
    int e = (c * 256 + tid) * 4;
    int b = e >> 5, yc = e & 31;
    int o = b * 64 + yc;
    float4 m = f4add(*(const float4*)(g_php + o), *(const float4*)(mean_b + yc));
    float4 s = f4add(*(const float4*)(g_php + o + 32), *(const float4*)(std_b + yc));
    float4 yv = *(const float4*)(y + (size_t)tt * (B_SZ * Y_DIM) + b * 32 + yc);
    const float LOG2PI = 1.8378770664093453f;
    float sv[4] = {s.x, s.y, s.z, s.w};
    float mv[4] = {m.x, m.y, m.z, m.w};
    float yy[4] = {yv.x, yv.y, yv.z, yv.w};
#pragma unroll
    for (int j = 0; j < 4; j++) {
        float std = (sv[j] > 15.0f) ? sv[j] : log1pf(expf(sv[j]));
        float diff = yy[j] - mv[j];
        nll_acc += 0.5f * (diff * diff / (std * std) + 2.0f * logf(std) + LOG2PI);
    }
}

__device__ __forceinline__ void p1_unit(SmemS* sm, int v,
                                        const float* dec_b1, const float* bhh0,
                                        const float* bhh1, int tid) {
    if (v < 64) {
        tile_gemm(sm, g_h1h, R_DIM, hw_d1, R_DIM, R_DIM,
                  (v >> 3) << 7, (v & 7) << 7, M_HRELU, dec_b1,
                  nullptr, g_d1h, H_DIM, tid);
    } else if (v < 160) {
        int w = v - 64, m = w / 12, n = w - m * 12;
        tile_gemm(sm, g_h0h, R_DIM, hw_g0, R_DIM, R_DIM,
                  m << 7, n << 7, M_FBIAS, bhh0, g_GH0, nullptr, R3, tid);
    } else {
        int w = v - 160, m = w / 12, n = w - m * 12;
        tile_gemm(sm, g_h1h, R_DIM, hw_g1, R_DIM, R_DIM,
                  m << 7, n << 7, M_FBIAS, bhh1, g_GH1, nullptr, R3, tid);
    }
}
__device__ __forceinline__ void heads_unit(SmemS* sm, int m, int tid) {
    tile_gemm(sm, g_d2h, H_DIM, hw_hd, H_DIM, H_DIM,
              m << 7, 0, M_FRAW64, nullptr, g_php, nullptr, 64, tid);
}

// ---------------- persistent kernel ----------------
__global__ __launch_bounds__(256, 1) void rnn_mma(
    const float* __restrict__ y,
    const float* __restrict__ dec_w1, const float* __restrict__ dec_b1,
    const float* __restrict__ dec_w2, const float* __restrict__ dec_b2,
    const float* __restrict__ mean_w, const float* __restrict__ mean_b,
    const float* __restrict__ std_w,  const float* __restrict__ std_b,
    const float* __restrict__ wih0,   const float* __restrict__ whh0,
    const float* __restrict__ bih0,   const float* __restrict__ bhh0,
    const float* __restrict__ wih1,   const float* __restrict__ whh1,
    const float* __restrict__ bih1,   const float* __restrict__ bhh1) {
    extern __shared__ char dynraw[];
    SmemS* sm = (SmemS*)dynraw;
    const int tid = threadIdx.x, bid = blockIdx.x, nb = gridDim.x;
    const int gs = nb * 256, gi = bid * 256 + tid;
    float nll_acc = 0.0f;

    // ---- one-time conversions ----
    for (int i = gi; i < H_DIM * R_DIM; i += gs) hw_d1[i] = __float2half(dec_w1[i]);
    for (int i = gi; i < H_DIM * H_DIM; i += gs) hw_d2[i] = __float2half(dec_w2[i]);
    for (int i = gi; i < 128 * H_DIM; i += gs) {
        int r = i >> 10, c = i & 1023;
        float v = (r < 32) ? mean_w[r * H_DIM + c] : (r < 64) ? std_w[(r - 32) * H_DIM + c] : 0.f;
        hw_hd[i] = __float2half(v);
    }
    for (int i = gi; i < R3 * YP; i += gs) {
        int r = i >> 6, c = i & 63;
        hw_i0[i] = (c < 32) ? __float2half(wih0[r * Y_DIM + c]) : __float2half(0.f);
    }
    for (int i = gi; i < R3 * R_DIM; i += gs) {
        hw_g0[i] = __float2half(whh0[i]);
        hw_i1[i] = __float2half(wih1[i]);
        hw_g1[i] = __float2half(whh1[i]);
    }
    for (int i = gi; i < B_SZ * R_DIM; i += gs) {
        g_h0[i] = 0.f; g_h1[i] = 0.f;
        g_h0h[i] = __float2half(0.f); g_h1h[i] = __float2half(0.f);
    }
    for (int i = gi; i < T_STEPS * B_SZ * YP; i += gs) {
        int c = i & 63, b = (i >> 6) & 1023, t = i >> 16;
        g_yh[i] = (c < 32) ? __float2half(y[(size_t)t * (B_SZ * Y_DIM) + b * 32 + c])
                           : __float2half(0.f);
    }
    unsigned int gen = 1;
    grid_sync(gen * nb);

    // ---- precompute GI0 (K=64) ----
    for (int u = bid; u < T_STEPS * 96; u += nb) {
        int t = u / 96, v = u - t * 96;
        int m = v / 12, n = v - m * 12;
        tile_gemm(sm, g_yh + (size_t)t * (B_SZ * YP), YP, hw_i0, YP, YP,
                  m << 7, n << 7, M_HBIAS, bih0,
                  nullptr, g_GI0 + (size_t)t * (B_SZ * R3), R3, tid);
    }
    gen++; grid_sync(gen * nb);

    for (int t = 0; t < T_STEPS; t++) {
        // P1: dec1(64) | GH0(96) | GH1(96) full-K + heads(t-1) at slots [116,124)
        if (t > 0) {
            for (int u = bid; u < 264; u += nb) {
                if (u >= 116 && u < 124) heads_unit(sm, u - 116, tid);
                else p1_unit(sm, (u < 116) ? u : u - 8, dec_b1, bhh0, bhh1, tid);
            }
        } else {
            for (int u = bid; u < 256; u += nb) p1_unit(sm, u, dec_b1, bhh0, bhh1, tid);
        }
        gen++; grid_sync(gen * nb);

        // P2 (light): gates0 (512) | nll(t-1) (32)
        int totP2 = 512 + ((t > 0) ? 32 : 0);
        for (int u = bid; u < totP2; u += nb) {
            if (u < 512) gates0v(t, u, tid);
            else nllv(y, mean_b, std_b, t - 1, u - 512, tid, nll_acc);
        }
        gen++; grid_sync(gen * nb);

        // P3: blocks [0,64): dec2 full-K; blocks [64,nb): GI1 full-K
        if (bid < 64) {
            tile_gemm(sm, g_d1h, H_DIM, hw_d2, H_DIM, H_DIM,
                      (bid >> 3) << 7, (bid & 7) << 7, M_HRELU, dec_b2,
                      nullptr, g_d2h, H_DIM, tid);
        } else {
            for (int u = bid - 64; u < 96; u += nb - 64) {
                int m = u / 12, n = u - m * 12;
                tile_gemm(sm, g_h0h, R_DIM, hw_i1, R_DIM, R_DIM,
                          m << 7, n << 7, M_FBIAS, bih1, g_GI1, nullptr, R3, tid);
            }
        }
        gen++; grid_sync(gen * nb);

        // P4 (light): gates1 (512)
        for (int u = bid; u < 512; u += nb) gates1v(u, tid);
        gen++; grid_sync(gen * nb);
    }

    // tail: heads(255) + nll(255)
    for (int u = bid; u < 8; u += nb) heads_unit(sm, u, tid);
    gen++; grid_sync(gen * nb);
    for (int u = bid; u < 32; u += nb) nllv(y, mean_b, std_b, 255, u, tid, nll_acc);

#pragma unroll
    for (int o = 16; o > 0; o >>= 1) nll_acc += __shfl_xor_sync(0xffffffffu, nll_acc, o);
    if ((tid & 31) == 0) sm->red[tid >> 5] = nll_acc;
    __syncthreads();
    if (tid == 0) {
        float s = 0.f;
#pragma unroll
        for (int i = 0; i < 8; i++) s += sm->red[i];
        g_nllb[bid] = (double)s;
    }
}

__global__ void finalize_kernel(float* out, int nblocks) {
    double s = 0.0;
    for (int i = 0; i < nblocks; i++) s += g_nllb[i];
    out[0] = (float)s;
    g_bar = 0u;
}

extern "C" void kernel_launch(void* const* d_in, const int* in_sizes, int n_in,
                              void* d_out, int out_size) {
    const float* y      = (const float*)d_in[0];
    const float* dec_w1 = (const float*)d_in[1];
    const float* dec_b1 = (const float*)d_in[2];
    const float* dec_w2 = (const float*)d_in[3];
    const float* dec_b2 = (const float*)d_in[4];
    const float* mean_w = (const float*)d_in[5];
    const float* mean_b = (const float*)d_in[6];
    const float* std_w  = (const float*)d_in[7];
    const float* std_b  = (const float*)d_in[8];
    const float* wih0   = (const float*)d_in[9];
    const float* whh0   = (const float*)d_in[10];
    const float* bih0   = (const float*)d_in[11];
    const float* bhh0   = (const float*)d_in[12];
    const float* wih1   = (const float*)d_in[13];
    const float* whh1   = (const float*)d_in[14];
    const float* bih1   = (const float*)d_in[15];
    const float* bhh1   = (const float*)d_in[16];

    cudaFuncSetAttribute(rnn_mma, cudaFuncAttributeMaxDynamicSharedMemorySize,
                         (int)sizeof(SmemS));
    int dev = 0, nsm = 0;
    cudaGetDevice(&dev);
    cudaDeviceGetAttribute(&nsm, cudaDevAttrMultiProcessorCount, dev);
    if (nsm > 512) nsm = 512;

    rnn_mma<<<nsm, 256, sizeof(SmemS)>>>(y, dec_w1, dec_b1, dec_w2, dec_b2,
                                         mean_w, mean_b, std_w, std_b,
                                         wih0, whh0, bih0, bhh0,
                                         wih1, whh1, bih1, bhh1);
    finalize_kernel<<<1, 1>>>((float*)d_out, nsm);
}